// round 12
// baseline (speedup 1.0000x reference)
#include <cuda_runtime.h>
#include <cuda_fp16.h>
#include <cstdint>

// B=2, S=1024, H=4096, NH=32, NKV=8, HD=128, GROUPS=4, M=B*S=2048
// Projection GEMMs: fp16 mma.m16n8k16 with FP16 accumulation per k64 chunk,
// promoted to fp32 master accumulators each chunk (hypothesis: f16-accum HMMA
// is 2x rate on sm_103 legacy path). Flash attention: R10 fp32-accum version.

// ---------------- scratch (static __device__, no allocations) ----------------
__device__ static __half g_Xh[2048 * 4096];           // fp16 X
__device__ static __half g_W [6144 * 4096];           // q,k,v weights fp16
__device__ static __half g_Wo[4096 * 4096];           // Wo fp16
__device__ static __half g_Q[2 * 32 * 1024 * 128];    // [B,NH,S,HD]
__device__ static __half g_K[2 * 8 * 1024 * 128];     // [B,NKV,S,HD]
__device__ static __half g_V[2 * 8 * 1024 * 128];     // [B,NKV,S,HD]
__device__ static __half g_AO[2048 * 4096];           // [B*S, NH*HD]

// ---------------- helpers ----------------
__device__ __forceinline__ void cpa16(void* dst, const void* src) {
    uint32_t s = static_cast<uint32_t>(__cvta_generic_to_shared(dst));
    asm volatile("cp.async.cg.shared.global [%0], [%1], 16;\n" :: "r"(s), "l"(src));
}
#define CP_COMMIT() asm volatile("cp.async.commit_group;\n")
#define CP_WAIT1()  asm volatile("cp.async.wait_group 1;\n")
#define CP_WAIT0()  asm volatile("cp.async.wait_group 0;\n")

__device__ __forceinline__ void mma_f16(float d[4], const uint32_t a[4], uint32_t b0, uint32_t b1) {
    asm volatile(
        "mma.sync.aligned.m16n8k16.row.col.f32.f16.f16.f32 "
        "{%0,%1,%2,%3},{%4,%5,%6,%7},{%8,%9},{%0,%1,%2,%3};\n"
        : "+f"(d[0]), "+f"(d[1]), "+f"(d[2]), "+f"(d[3])
        : "r"(a[0]), "r"(a[1]), "r"(a[2]), "r"(a[3]), "r"(b0), "r"(b1));
}
// fp16-accumulator variant: d/c are 2 packed b32 regs
__device__ __forceinline__ void mma_f16h(uint32_t d[2], const uint32_t a[4], uint32_t b0, uint32_t b1) {
    asm volatile(
        "mma.sync.aligned.m16n8k16.row.col.f16.f16.f16.f16 "
        "{%0,%1},{%2,%3,%4,%5},{%6,%7},{%0,%1};\n"
        : "+r"(d[0]), "+r"(d[1])
        : "r"(a[0]), "r"(a[1]), "r"(a[2]), "r"(a[3]), "r"(b0), "r"(b1));
}
__device__ __forceinline__ void ldm4(uint32_t r[4], uint32_t addr) {
    asm volatile("ldmatrix.sync.aligned.m8n8.x4.shared.b16 {%0,%1,%2,%3}, [%4];"
        : "=r"(r[0]), "=r"(r[1]), "=r"(r[2]), "=r"(r[3]) : "r"(addr));
}
__device__ __forceinline__ void ldm4t(uint32_t r[4], uint32_t addr) {
    asm volatile("ldmatrix.sync.aligned.m8n8.x4.trans.shared.b16 {%0,%1,%2,%3}, [%4];"
        : "=r"(r[0]), "=r"(r[1]), "=r"(r[2]), "=r"(r[3]) : "r"(addr));
}
__device__ __forceinline__ uint32_t ldu32(const __half* p) {
    return *reinterpret_cast<const uint32_t*>(p);
}

// ---------------- prep kernels ----------------
__global__ __launch_bounds__(256) void w2h_kernel(const int* __restrict__ src,
                                                  __half* __restrict__ dst, int n8) {
    int i = blockIdx.x * 256 + threadIdx.x;
    if (i >= n8) return;
    const int4* s = reinterpret_cast<const int4*>(src) + i * 2;
    int4 a = s[0], b = s[1];
    __half h[8];
    h[0] = __int2half_rn(a.x); h[1] = __int2half_rn(a.y);
    h[2] = __int2half_rn(a.z); h[3] = __int2half_rn(a.w);
    h[4] = __int2half_rn(b.x); h[5] = __int2half_rn(b.y);
    h[6] = __int2half_rn(b.z); h[7] = __int2half_rn(b.w);
    reinterpret_cast<uint4*>(dst)[i] = *reinterpret_cast<const uint4*>(h);
}
__global__ __launch_bounds__(256) void x2h_kernel(const float* __restrict__ src,
                                                  __half* __restrict__ dst, int n8) {
    int i = blockIdx.x * 256 + threadIdx.x;
    if (i >= n8) return;
    const float4* s = reinterpret_cast<const float4*>(src) + i * 2;
    float4 a = s[0], b = s[1];
    __half h[8];
    h[0] = __float2half_rn(a.x); h[1] = __float2half_rn(a.y);
    h[2] = __float2half_rn(a.z); h[3] = __float2half_rn(a.w);
    h[4] = __float2half_rn(b.x); h[5] = __float2half_rn(b.y);
    h[6] = __float2half_rn(b.z); h[7] = __float2half_rn(b.w);
    reinterpret_cast<uint4*>(dst)[i] = *reinterpret_cast<const uint4*>(h);
}

// ---------------- fp16 GEMM core ----------------
// CTA 256x128, kc=64 halves, 3-stage pipeline. pitch 72 halves (144 B).
#define HP 72
#define AH (256 * HP)
#define BH (128 * HP)
#define BUFH (AH + BH)
#define SMEM_H3 (3 * BUFH * 2)        // 165888 B

__device__ __forceinline__ void load_tileA_h(__half* dst, const __half* src, int rs, int t) {
    int c = t & 7, mb = t >> 3;
#pragma unroll
    for (int p = 0; p < 8; ++p) {
        int m = mb + 32 * p;
        cpa16(dst + m * HP + 8 * c, src + (size_t)m * rs + 8 * c);
    }
}
__device__ __forceinline__ void load_tileB_h(__half* dst, const __half* src, int rs, int t) {
    int c = t & 7, nb = t >> 3;
#pragma unroll
    for (int p = 0; p < 4; ++p) {
        int n = nb + 32 * p;
        cpa16(dst + n * HP + 8 * c, src + (size_t)n * rs + 8 * c);
    }
}

// one kc=64 chunk: fp16 accumulation within chunk, promote to fp32 at end.
__device__ __forceinline__ void compute_h64h(uint32_t sAa, uint32_t sBa,
                                             float acc[4][8][4], int lane, int wm, int wn) {
    const int arow = ((lane >> 3) & 1) * 8 + (lane & 7);
    const int acol = ((lane >> 4) & 1) * 8;
    const int brow = ((lane >> 4) & 1) * 8 + (lane & 7);
    const int bcol = ((lane >> 3) & 1) * 8;

    uint32_t hacc[4][8][2];
#pragma unroll
    for (int i = 0; i < 4; ++i)
#pragma unroll
        for (int j = 0; j < 8; ++j) { hacc[i][j][0] = 0u; hacc[i][j][1] = 0u; }

#pragma unroll
    for (int ks = 0; ks < 4; ++ks) {
        uint32_t af[4][4], bf[4][4];
#pragma unroll
        for (int i = 0; i < 4; ++i)
            ldm4(af[i], sAa + ((wm + 16 * i + arow) * HP + 16 * ks + acol) * 2);
#pragma unroll
        for (int jj = 0; jj < 4; ++jj)
            ldm4(bf[jj], sBa + ((wn + 16 * jj + brow) * HP + 16 * ks + bcol) * 2);
#pragma unroll
        for (int i = 0; i < 4; ++i)
#pragma unroll
            for (int jj = 0; jj < 4; ++jj) {
                mma_f16h(hacc[i][2 * jj],     af[i], bf[jj][0], bf[jj][1]);
                mma_f16h(hacc[i][2 * jj + 1], af[i], bf[jj][2], bf[jj][3]);
            }
    }
    // promote chunk sums into fp32 master accumulators
#pragma unroll
    for (int i = 0; i < 4; ++i)
#pragma unroll
        for (int j = 0; j < 8; ++j) {
            float2 lo = __half22float2(*reinterpret_cast<__half2*>(&hacc[i][j][0]));
            float2 hi = __half22float2(*reinterpret_cast<__half2*>(&hacc[i][j][1]));
            acc[i][j][0] += lo.x;
            acc[i][j][1] += lo.y;
            acc[i][j][2] += hi.x;
            acc[i][j][3] += hi.y;
        }
}

// ---------------- GEMM 1: fused QKV projection ---------------- grid (8m, 48n)
__global__ __launch_bounds__(256) void qkv_h(
    const float* __restrict__ sq, const float* __restrict__ bq,
    const float* __restrict__ sk, const float* __restrict__ bk,
    const float* __restrict__ sv)
{
    extern __shared__ __half smh[];
    const uint32_t sbase = static_cast<uint32_t>(__cvta_generic_to_shared(smh));
    const int t = threadIdx.x, lane = t & 31, w = t >> 5;
    const int wm = (w >> 1) * 64, wn = (w & 1) * 64;
    const int m0 = blockIdx.x * 256, n0 = blockIdx.y * 128;

    float acc[4][8][4];
#pragma unroll
    for (int i = 0; i < 4; ++i)
#pragma unroll
        for (int j = 0; j < 8; ++j)
#pragma unroll
            for (int q = 0; q < 4; ++q) acc[i][j][q] = 0.f;

    const __half* Ab = g_Xh + (size_t)m0 * 4096;
    const __half* Bb = g_W + (size_t)n0 * 4096;

    load_tileA_h(smh, Ab, 4096, t);
    load_tileB_h(smh + AH, Bb, 4096, t);
    CP_COMMIT();
    load_tileA_h(smh + BUFH, Ab + 64, 4096, t);
    load_tileB_h(smh + BUFH + AH, Bb + 64, 4096, t);
    CP_COMMIT();
    for (int it = 0; it < 64; ++it) {
        CP_WAIT1();
        __syncthreads();
        if (it + 2 < 64) {
            int nb = (it + 2) % 3;
            load_tileA_h(smh + nb * BUFH, Ab + (it + 2) * 64, 4096, t);
            load_tileB_h(smh + nb * BUFH + AH, Bb + (it + 2) * 64, 4096, t);
        }
        CP_COMMIT();
        uint32_t boff = sbase + (uint32_t)((it % 3) * BUFH * 2);
        compute_h64h(boff, boff + AH * 2, acc, lane, wm, wn);
    }

    // epilogue: dequant + bias + fp16 round + head scatter
    int region, nloc;
    const float* scale; const float* bias;
    if (n0 < 4096)      { region = 0; nloc = n0;        scale = sq; bias = bq; }
    else if (n0 < 5120) { region = 1; nloc = n0 - 4096; scale = sk; bias = bk; }
    else                { region = 2; nloc = n0 - 5120; scale = sv; bias = nullptr; }
    const int head = nloc >> 7;
    const int lr = lane >> 2, lc = lane & 3;
#pragma unroll
    for (int j = 0; j < 8; ++j) {
        int col = wn + 8 * j + 2 * lc;
        int nl = nloc + col;
        float sc0 = scale[nl], sc1 = scale[nl + 1];
        float bb0 = bias ? bias[nl] : 0.f, bb1 = bias ? bias[nl + 1] : 0.f;
#pragma unroll
        for (int i = 0; i < 4; ++i) {
#pragma unroll
            for (int h2 = 0; h2 < 2; ++h2) {
                int m = m0 + wm + 16 * i + lr + 8 * h2;
                int b = m >> 10, s = m & 1023;
                float v0 = acc[i][j][2 * h2 + 0] * sc0 + bb0;
                float v1 = acc[i][j][2 * h2 + 1] * sc1 + bb1;
                __half* dst;
                if (region == 0)      dst = g_Q + ((size_t)((b * 32 + head) * 1024 + s)) * 128 + col;
                else if (region == 1) dst = g_K + ((size_t)((b * 8 + head) * 1024 + s)) * 128 + col;
                else                  dst = g_V + ((size_t)((b * 8 + head) * 1024 + s)) * 128 + col;
                *reinterpret_cast<__half2*>(dst) = __floats2half2_rn(v0, v1);
            }
        }
    }
}

// ---------------- fused causal flash attention (fp16, R10) ---- grid (64, 8)
#define FKH 136
#define FVH 136
#define FPH 72
#define SKH (64 * FKH)
#define SVH (64 * FVH)
#define FLASH_SMEM ((2 * SKH + 2 * SVH + 128 * FPH) * 2)

__device__ __forceinline__ void flash_loadT(__half* dst, const __half* src, int n0, int t) {
    int c = t & 15, rb = t >> 4;
#pragma unroll
    for (int p = 0; p < 4; ++p) {
        int r = rb + 16 * p;
        cpa16(dst + r * FKH + 8 * c, src + (size_t)(n0 + r) * 128 + 8 * c);
    }
}

__global__ __launch_bounds__(256, 1) void flash_h()
{
    extern __shared__ __half smh[];
    __half* sK = smh;
    __half* sV = smh + 2 * SKH;
    __half* sP = sV + 2 * SVH;
    const uint32_t sKa0 = static_cast<uint32_t>(__cvta_generic_to_shared(sK));
    const uint32_t sVa0 = static_cast<uint32_t>(__cvta_generic_to_shared(sV));
    const uint32_t sPa  = static_cast<uint32_t>(__cvta_generic_to_shared(sP));

    const int t = threadIdx.x, lane = t & 31, w = t >> 5;
    const int lr = lane >> 2, lc = lane & 3;
    const int arow = ((lane >> 3) & 1) * 8 + (lane & 7);
    const int acol = ((lane >> 4) & 1) * 8;
    const int brow = ((lane >> 4) & 1) * 8 + (lane & 7);
    const int bcol = ((lane >> 3) & 1) * 8;
    const int z = blockIdx.x, mt = 7 - blockIdx.y;
    const int m0 = mt * 128;
    const int niter = 2 * mt + 2;
    const int b = z >> 5, h = z & 31, kvh = h >> 2;

    const __half* Qp = g_Q + (size_t)(b * 32 + h) * 131072;
    const __half* Kp = g_K + (size_t)(b * 8 + kvh) * 131072;
    const __half* Vp = g_V + (size_t)(b * 8 + kvh) * 131072;

    {
        int c = t & 15, rb = t >> 4;
#pragma unroll
        for (int p = 0; p < 8; ++p) {
            int r = rb + 16 * p;
            __half* dst = (r < 64) ? (sK + r * FKH + 8 * c)
                                   : (sV + (r - 64) * FKH + 8 * c);
            cpa16(dst, Qp + (size_t)(m0 + r) * 128 + 8 * c);
        }
        CP_COMMIT(); CP_WAIT0();
    }
    __syncthreads();

    uint32_t qf[8][4];
    {
        const __half* base = (w < 4) ? sK : sV;
        int rb2 = (w < 4) ? 16 * w : 16 * w - 64;
#pragma unroll
        for (int s = 0; s < 8; ++s) {
            const __half* p = base + (rb2 + lr) * FKH + 16 * s + 2 * lc;
            qf[s][0] = ldu32(p);
            qf[s][1] = ldu32(p + 8 * FKH);
            qf[s][2] = ldu32(p + 8);
            qf[s][3] = ldu32(p + 8 * FKH + 8);
        }
    }
    __syncthreads();

    float oacc[16][4];
#pragma unroll
    for (int j = 0; j < 16; ++j)
#pragma unroll
        for (int q = 0; q < 4; ++q) oacc[j][q] = 0.f;
    float mrow[2] = {-1e38f, -1e38f};
    float lrow[2] = {0.f, 0.f};

    flash_loadT(sK, Kp, 0, t);
    flash_loadT(sV, Vp, 0, t);
    CP_COMMIT();

    const float sscale = 0.08838834764831845f;

    for (int it = 0; it < niter; ++it) {
        if (it + 1 < niter) {
            int nb = (it + 1) & 1;
            flash_loadT(sK + nb * SKH, Kp, (it + 1) * 64, t);
            flash_loadT(sV + nb * SVH, Vp, (it + 1) * 64, t);
            CP_COMMIT(); CP_WAIT1();
        } else CP_WAIT0();
        __syncthreads();

        const int buf = it & 1;
        const uint32_t K0a = sKa0 + buf * SKH * 2;
        const uint32_t V0a = sVa0 + buf * SVH * 2;
        const int n0 = it * 64;

        float sacc[8][4];
#pragma unroll
        for (int j = 0; j < 8; ++j)
#pragma unroll
            for (int q = 0; q < 4; ++q) sacc[j][q] = 0.f;
#pragma unroll
        for (int s = 0; s < 8; ++s) {
            uint32_t kf[4][4];
#pragma unroll
            for (int jj = 0; jj < 4; ++jj)
                ldm4(kf[jj], K0a + ((16 * jj + brow) * FKH + 16 * s + bcol) * 2);
#pragma unroll
            for (int jj = 0; jj < 4; ++jj) {
                mma_f16(sacc[2 * jj],     qf[s], kf[jj][0], kf[jj][1]);
                mma_f16(sacc[2 * jj + 1], qf[s], kf[jj][2], kf[jj][3]);
            }
        }

#pragma unroll
        for (int d = 0; d < 2; ++d) {
            const int grow = m0 + 16 * w + lr + 8 * d;
            float rm = -1e38f;
#pragma unroll
            for (int j = 0; j < 8; ++j) {
                int c0 = n0 + 8 * j + 2 * lc;
                float v0 = sacc[j][2 * d]     * sscale;
                float v1 = sacc[j][2 * d + 1] * sscale;
                if (c0     > grow) v0 = -1e30f;
                if (c0 + 1 > grow) v1 = -1e30f;
                sacc[j][2 * d]     = v0;
                sacc[j][2 * d + 1] = v1;
                rm = fmaxf(rm, fmaxf(v0, v1));
            }
            rm = fmaxf(rm, __shfl_xor_sync(0xffffffffu, rm, 1));
            rm = fmaxf(rm, __shfl_xor_sync(0xffffffffu, rm, 2));
            float newm = fmaxf(mrow[d], rm);
            float f = __expf(mrow[d] - newm);
            float rs = 0.f;
#pragma unroll
            for (int j = 0; j < 8; ++j) {
                float p0 = __expf(sacc[j][2 * d]     - newm);
                float p1 = __expf(sacc[j][2 * d + 1] - newm);
                rs += p0 + p1;
                __half2* pp = reinterpret_cast<__half2*>(
                    sP + (16 * w + lr + 8 * d) * FPH + 8 * j + 2 * lc);
                *pp = __floats2half2_rn(p0, p1);
            }
            rs += __shfl_xor_sync(0xffffffffu, rs, 1);
            rs += __shfl_xor_sync(0xffffffffu, rs, 2);
            lrow[d] = lrow[d] * f + rs;
            mrow[d] = newm;
#pragma unroll
            for (int j2 = 0; j2 < 16; ++j2) {
                oacc[j2][2 * d]     *= f;
                oacc[j2][2 * d + 1] *= f;
            }
        }
        __syncwarp();

#pragma unroll
        for (int s = 0; s < 4; ++s) {
            uint32_t af[4];
            ldm4(af, sPa + ((16 * w + arow) * FPH + 16 * s + acol) * 2);
#pragma unroll
            for (int jj = 0; jj < 8; ++jj) {
                uint32_t vf[4];
                ldm4t(vf, V0a + ((16 * s + arow) * FVH + 16 * jj + acol) * 2);
                mma_f16(oacc[2 * jj],     af, vf[0], vf[1]);
                mma_f16(oacc[2 * jj + 1], af, vf[2], vf[3]);
            }
        }
        __syncthreads();
    }

#pragma unroll
    for (int d = 0; d < 2; ++d) {
        float inv = 1.f / lrow[d];
        int grow = m0 + 16 * w + lr + 8 * d;
        __half* orow = g_AO + ((size_t)(b * 1024 + grow)) * 4096 + h * 128;
#pragma unroll
        for (int j2 = 0; j2 < 16; ++j2) {
            __half2* dst = reinterpret_cast<__half2*>(orow + 8 * j2 + 2 * lc);
            *dst = __floats2half2_rn(oacc[j2][2 * d] * inv, oacc[j2][2 * d + 1] * inv);
        }
    }
}

// ---------------- GEMM 4: out = AO @ Wo^T * so ---------------- grid (8m, 32n)
__global__ __launch_bounds__(256) void o_h(const float* __restrict__ so,
                                           float* __restrict__ out)
{
    extern __shared__ __half smh[];
    const uint32_t sbase = static_cast<uint32_t>(__cvta_generic_to_shared(smh));
    const int t = threadIdx.x, lane = t & 31, w = t >> 5;
    const int wm = (w >> 1) * 64, wn = (w & 1) * 64;
    const int m0 = blockIdx.x * 256, n0 = blockIdx.y * 128;

    float acc[4][8][4];
#pragma unroll
    for (int i = 0; i < 4; ++i)
#pragma unroll
        for (int j = 0; j < 8; ++j)
#pragma unroll
            for (int q = 0; q < 4; ++q) acc[i][j][q] = 0.f;

    const __half* Ab = g_AO + (size_t)m0 * 4096;
    const __half* Bb = g_Wo + (size_t)n0 * 4096;

    load_tileA_h(smh, Ab, 4096, t);
    load_tileB_h(smh + AH, Bb, 4096, t);
    CP_COMMIT();
    load_tileA_h(smh + BUFH, Ab + 64, 4096, t);
    load_tileB_h(smh + BUFH + AH, Bb + 64, 4096, t);
    CP_COMMIT();
    for (int it = 0; it < 64; ++it) {
        CP_WAIT1();
        __syncthreads();
        if (it + 2 < 64) {
            int nb = (it + 2) % 3;
            load_tileA_h(smh + nb * BUFH, Ab + (it + 2) * 64, 4096, t);
            load_tileB_h(smh + nb * BUFH + AH, Bb + (it + 2) * 64, 4096, t);
        }
        CP_COMMIT();
        uint32_t boff = sbase + (uint32_t)((it % 3) * BUFH * 2);
        compute_h64h(boff, boff + AH * 2, acc, lane, wm, wn);
    }

    const int lr = lane >> 2, lc = lane & 3;
#pragma unroll
    for (int j = 0; j < 8; ++j) {
        int col = n0 + wn + 8 * j + 2 * lc;
        float sc0 = so[col], sc1 = so[col + 1];
#pragma unroll
        for (int i = 0; i < 4; ++i) {
#pragma unroll
            for (int h2 = 0; h2 < 2; ++h2) {
                int m = m0 + wm + 16 * i + lr + 8 * h2;
                float2 o = make_float2(acc[i][j][2 * h2 + 0] * sc0,
                                       acc[i][j][2 * h2 + 1] * sc1);
                *reinterpret_cast<float2*>(out + (size_t)m * 4096 + col) = o;
            }
        }
    }
}

// =============================================================================
extern "C" void kernel_launch(void* const* d_in, const int* in_sizes, int n_in,
                              void* d_out, int out_size)
{
    const float* X    = (const float*)d_in[0];
    const float* sq   = (const float*)d_in[3];
    const float* bq   = (const float*)d_in[4];
    const float* sk   = (const float*)d_in[6];
    const float* bk   = (const float*)d_in[7];
    const float* sv   = (const float*)d_in[9];
    const float* so   = (const float*)d_in[11];
    const int*   wq   = (const int*)d_in[2];
    const int*   wk   = (const int*)d_in[5];
    const int*   wv   = (const int*)d_in[8];
    const int*   wo   = (const int*)d_in[10];
    float* out = (float*)d_out;

    cudaFuncSetAttribute(qkv_h,   cudaFuncAttributeMaxDynamicSharedMemorySize, SMEM_H3);
    cudaFuncSetAttribute(o_h,     cudaFuncAttributeMaxDynamicSharedMemorySize, SMEM_H3);
    cudaFuncSetAttribute(flash_h, cudaFuncAttributeMaxDynamicSharedMemorySize, FLASH_SMEM);

    __half* Xh = nullptr; cudaGetSymbolAddress((void**)&Xh, g_Xh);
    __half* W  = nullptr; cudaGetSymbolAddress((void**)&W,  g_W);
    __half* Wo = nullptr; cudaGetSymbolAddress((void**)&Wo, g_Wo);

    x2h_kernel<<<(2048 * 4096 / 8 + 255) / 256, 256>>>(X, Xh, 2048 * 4096 / 8);
    w2h_kernel<<<(4096 * 4096 / 8 + 255) / 256, 256>>>(wq, W,               4096 * 4096 / 8);
    w2h_kernel<<<(1024 * 4096 / 8 + 255) / 256, 256>>>(wk, W + 4096 * 4096, 1024 * 4096 / 8);
    w2h_kernel<<<(1024 * 4096 / 8 + 255) / 256, 256>>>(wv, W + 5120 * 4096, 1024 * 4096 / 8);
    w2h_kernel<<<(4096 * 4096 / 8 + 255) / 256, 256>>>(wo, Wo,              4096 * 4096 / 8);

    qkv_h<<<dim3(8, 48), 256, SMEM_H3>>>(sq, bq, sk, bk, sv);
    flash_h<<<dim3(64, 8), 256, FLASH_SMEM>>>();
    o_h<<<dim3(8, 32), 256, SMEM_H3>>>(so, out);
}

// round 15
// speedup vs baseline: 1.1345x; 1.1345x over previous
#include <cuda_runtime.h>
#include <cuda_fp16.h>
#include <cstdint>

// B=2, S=1024, H=4096, NH=32, NKV=8, HD=128, GROUPS=4, M=B*S=2048
// All GEMMs: fp16 mma.m16n8k16 + fp32 accum, ldmatrix feeds.
// Projection GEMMs: 128x128 CTA tiles, 3-stage cp.async, 2 CTAs/SM.
// Flash attention: R10 version (unchanged).

// ---------------- scratch (static __device__, no allocations) ----------------
__device__ static __half g_Xh[2048 * 4096];           // fp16 X
__device__ static __half g_W [6144 * 4096];           // q,k,v weights fp16
__device__ static __half g_Wo[4096 * 4096];           // Wo fp16
__device__ static __half g_Q[2 * 32 * 1024 * 128];    // [B,NH,S,HD]
__device__ static __half g_K[2 * 8 * 1024 * 128];     // [B,NKV,S,HD]
__device__ static __half g_V[2 * 8 * 1024 * 128];     // [B,NKV,S,HD]
__device__ static __half g_AO[2048 * 4096];           // [B*S, NH*HD]

// ---------------- helpers ----------------
__device__ __forceinline__ void cpa16(void* dst, const void* src) {
    uint32_t s = static_cast<uint32_t>(__cvta_generic_to_shared(dst));
    asm volatile("cp.async.cg.shared.global [%0], [%1], 16;\n" :: "r"(s), "l"(src));
}
#define CP_COMMIT() asm volatile("cp.async.commit_group;\n")
#define CP_WAIT1()  asm volatile("cp.async.wait_group 1;\n")
#define CP_WAIT0()  asm volatile("cp.async.wait_group 0;\n")

__device__ __forceinline__ void mma_f16(float d[4], const uint32_t a[4], uint32_t b0, uint32_t b1) {
    asm volatile(
        "mma.sync.aligned.m16n8k16.row.col.f32.f16.f16.f32 "
        "{%0,%1,%2,%3},{%4,%5,%6,%7},{%8,%9},{%0,%1,%2,%3};\n"
        : "+f"(d[0]), "+f"(d[1]), "+f"(d[2]), "+f"(d[3])
        : "r"(a[0]), "r"(a[1]), "r"(a[2]), "r"(a[3]), "r"(b0), "r"(b1));
}
__device__ __forceinline__ void ldm4(uint32_t r[4], uint32_t addr) {
    asm volatile("ldmatrix.sync.aligned.m8n8.x4.shared.b16 {%0,%1,%2,%3}, [%4];"
        : "=r"(r[0]), "=r"(r[1]), "=r"(r[2]), "=r"(r[3]) : "r"(addr));
}
__device__ __forceinline__ void ldm4t(uint32_t r[4], uint32_t addr) {
    asm volatile("ldmatrix.sync.aligned.m8n8.x4.trans.shared.b16 {%0,%1,%2,%3}, [%4];"
        : "=r"(r[0]), "=r"(r[1]), "=r"(r[2]), "=r"(r[3]) : "r"(addr));
}
__device__ __forceinline__ uint32_t ldu32(const __half* p) {
    return *reinterpret_cast<const uint32_t*>(p);
}

// ---------------- prep kernels (32 values/thread, MLP=8) ----------------
__global__ __launch_bounds__(256) void w2h_kernel(const int* __restrict__ src,
                                                  __half* __restrict__ dst, int n32) {
    int i = blockIdx.x * 256 + threadIdx.x;
    if (i >= n32) return;
    const int4* s = reinterpret_cast<const int4*>(src) + (size_t)i * 8;
    int4 v[8];
#pragma unroll
    for (int k = 0; k < 8; ++k) v[k] = s[k];
    __half h[32];
#pragma unroll
    for (int k = 0; k < 8; ++k) {
        h[4 * k + 0] = __int2half_rn(v[k].x);
        h[4 * k + 1] = __int2half_rn(v[k].y);
        h[4 * k + 2] = __int2half_rn(v[k].z);
        h[4 * k + 3] = __int2half_rn(v[k].w);
    }
    uint4* d = reinterpret_cast<uint4*>(dst) + (size_t)i * 4;
    const uint4* hs = reinterpret_cast<const uint4*>(h);
#pragma unroll
    for (int k = 0; k < 4; ++k) d[k] = hs[k];
}
__global__ __launch_bounds__(256) void x2h_kernel(const float* __restrict__ src,
                                                  __half* __restrict__ dst, int n32) {
    int i = blockIdx.x * 256 + threadIdx.x;
    if (i >= n32) return;
    const float4* s = reinterpret_cast<const float4*>(src) + (size_t)i * 8;
    float4 v[8];
#pragma unroll
    for (int k = 0; k < 8; ++k) v[k] = s[k];
    __half h[32];
#pragma unroll
    for (int k = 0; k < 8; ++k) {
        h[4 * k + 0] = __float2half_rn(v[k].x);
        h[4 * k + 1] = __float2half_rn(v[k].y);
        h[4 * k + 2] = __float2half_rn(v[k].z);
        h[4 * k + 3] = __float2half_rn(v[k].w);
    }
    uint4* d = reinterpret_cast<uint4*>(dst) + (size_t)i * 4;
    const uint4* hs = reinterpret_cast<const uint4*>(h);
#pragma unroll
    for (int k = 0; k < 4; ++k) d[k] = hs[k];
}

// ---------------- fp16 GEMM core: CTA 128x128, kc=64, 3 stages, occ 2 ----------
#define HP 72
#define TH (128 * HP)                 // halves per (A or B) tile
#define BUFH (2 * TH)                 // halves per stage
#define SMEM_G (3 * BUFH * 2)         // 110592 B

// load one 128x64 tile (A or B), 256 threads, 4 cp.async each
__device__ __forceinline__ void load_tile128(__half* dst, const __half* src, int t) {
    int c = t & 7, r0 = t >> 3;
#pragma unroll
    for (int p = 0; p < 4; ++p) {
        int r = r0 + 32 * p;
        cpa16(dst + r * HP + 8 * c, src + (size_t)r * 4096 + 8 * c);
    }
}

// one kc=64 chunk: warp tile 64x32 (4 m-tiles x 4 n8-groups)
__device__ __forceinline__ void compute_g64(uint32_t sAa, uint32_t sBa,
                                            float acc[4][4][4], int lane, int wm, int wn) {
    const int arow = ((lane >> 3) & 1) * 8 + (lane & 7);
    const int acol = ((lane >> 4) & 1) * 8;
    const int brow = ((lane >> 4) & 1) * 8 + (lane & 7);
    const int bcol = ((lane >> 3) & 1) * 8;
#pragma unroll
    for (int ks = 0; ks < 4; ++ks) {
        uint32_t af[4][4], bf[2][4];
#pragma unroll
        for (int i = 0; i < 4; ++i)
            ldm4(af[i], sAa + ((wm + 16 * i + arow) * HP + 16 * ks + acol) * 2);
#pragma unroll
        for (int jj = 0; jj < 2; ++jj)
            ldm4(bf[jj], sBa + ((wn + 16 * jj + brow) * HP + 16 * ks + bcol) * 2);
#pragma unroll
        for (int i = 0; i < 4; ++i)
#pragma unroll
            for (int jj = 0; jj < 2; ++jj) {
                mma_f16(acc[i][2 * jj],     af[i], bf[jj][0], bf[jj][1]);
                mma_f16(acc[i][2 * jj + 1], af[i], bf[jj][2], bf[jj][3]);
            }
    }
}

// ---------------- GEMM 1: fused QKV projection ---------------- grid (16m, 48n)
__global__ __launch_bounds__(256, 2) void qkv_h(
    const float* __restrict__ sq, const float* __restrict__ bq,
    const float* __restrict__ sk, const float* __restrict__ bk,
    const float* __restrict__ sv)
{
    extern __shared__ __half smh[];
    const uint32_t sbase = static_cast<uint32_t>(__cvta_generic_to_shared(smh));
    const int t = threadIdx.x, lane = t & 31, w = t >> 5;
    const int wm = (w >> 2) * 64, wn = (w & 3) * 32;
    const int m0 = blockIdx.x * 128, n0 = blockIdx.y * 128;

    float acc[4][4][4];
#pragma unroll
    for (int i = 0; i < 4; ++i)
#pragma unroll
        for (int j = 0; j < 4; ++j)
#pragma unroll
            for (int q = 0; q < 4; ++q) acc[i][j][q] = 0.f;

    const __half* Ab = g_Xh + (size_t)m0 * 4096;
    const __half* Bb = g_W + (size_t)n0 * 4096;

    load_tile128(smh, Ab, t);
    load_tile128(smh + TH, Bb, t);
    CP_COMMIT();
    load_tile128(smh + BUFH, Ab + 64, t);
    load_tile128(smh + BUFH + TH, Bb + 64, t);
    CP_COMMIT();
    for (int it = 0; it < 64; ++it) {
        CP_WAIT1();
        __syncthreads();
        if (it + 2 < 64) {
            int nb = (it + 2) % 3;
            load_tile128(smh + nb * BUFH, Ab + (it + 2) * 64, t);
            load_tile128(smh + nb * BUFH + TH, Bb + (it + 2) * 64, t);
        }
        CP_COMMIT();
        uint32_t boff = sbase + (uint32_t)((it % 3) * BUFH * 2);
        compute_g64(boff, boff + TH * 2, acc, lane, wm, wn);
    }

    // epilogue: dequant + bias + fp16 round + head scatter
    int region, nloc;
    const float* scale; const float* bias;
    if (n0 < 4096)      { region = 0; nloc = n0;        scale = sq; bias = bq; }
    else if (n0 < 5120) { region = 1; nloc = n0 - 4096; scale = sk; bias = bk; }
    else                { region = 2; nloc = n0 - 5120; scale = sv; bias = nullptr; }
    const int head = nloc >> 7;
    const int lr = lane >> 2, lc = lane & 3;
#pragma unroll
    for (int j = 0; j < 4; ++j) {
        int col = wn + 8 * j + 2 * lc;
        int nl = nloc + col;
        float sc0 = scale[nl], sc1 = scale[nl + 1];
        float bb0 = bias ? bias[nl] : 0.f, bb1 = bias ? bias[nl + 1] : 0.f;
#pragma unroll
        for (int i = 0; i < 4; ++i) {
#pragma unroll
            for (int h2 = 0; h2 < 2; ++h2) {
                int m = m0 + wm + 16 * i + lr + 8 * h2;
                int b = m >> 10, s = m & 1023;
                float v0 = acc[i][j][2 * h2 + 0] * sc0 + bb0;
                float v1 = acc[i][j][2 * h2 + 1] * sc1 + bb1;
                __half* dst;
                if (region == 0)      dst = g_Q + ((size_t)((b * 32 + head) * 1024 + s)) * 128 + col;
                else if (region == 1) dst = g_K + ((size_t)((b * 8 + head) * 1024 + s)) * 128 + col;
                else                  dst = g_V + ((size_t)((b * 8 + head) * 1024 + s)) * 128 + col;
                *reinterpret_cast<__half2*>(dst) = __floats2half2_rn(v0, v1);
            }
        }
    }
}

// ---------------- GEMM 4: out = AO @ Wo^T * so ---------------- grid (16m, 32n)
__global__ __launch_bounds__(256, 2) void o_h(const float* __restrict__ so,
                                              float* __restrict__ out)
{
    extern __shared__ __half smh[];
    const uint32_t sbase = static_cast<uint32_t>(__cvta_generic_to_shared(smh));
    const int t = threadIdx.x, lane = t & 31, w = t >> 5;
    const int wm = (w >> 2) * 64, wn = (w & 3) * 32;
    const int m0 = blockIdx.x * 128, n0 = blockIdx.y * 128;

    float acc[4][4][4];
#pragma unroll
    for (int i = 0; i < 4; ++i)
#pragma unroll
        for (int j = 0; j < 4; ++j)
#pragma unroll
            for (int q = 0; q < 4; ++q) acc[i][j][q] = 0.f;

    const __half* Ab = g_AO + (size_t)m0 * 4096;
    const __half* Bb = g_Wo + (size_t)n0 * 4096;

    load_tile128(smh, Ab, t);
    load_tile128(smh + TH, Bb, t);
    CP_COMMIT();
    load_tile128(smh + BUFH, Ab + 64, t);
    load_tile128(smh + BUFH + TH, Bb + 64, t);
    CP_COMMIT();
    for (int it = 0; it < 64; ++it) {
        CP_WAIT1();
        __syncthreads();
        if (it + 2 < 64) {
            int nb = (it + 2) % 3;
            load_tile128(smh + nb * BUFH, Ab + (it + 2) * 64, t);
            load_tile128(smh + nb * BUFH + TH, Bb + (it + 2) * 64, t);
        }
        CP_COMMIT();
        uint32_t boff = sbase + (uint32_t)((it % 3) * BUFH * 2);
        compute_g64(boff, boff + TH * 2, acc, lane, wm, wn);
    }

    const int lr = lane >> 2, lc = lane & 3;
#pragma unroll
    for (int j = 0; j < 4; ++j) {
        int col = n0 + wn + 8 * j + 2 * lc;
        float sc0 = so[col], sc1 = so[col + 1];
#pragma unroll
        for (int i = 0; i < 4; ++i) {
#pragma unroll
            for (int h2 = 0; h2 < 2; ++h2) {
                int m = m0 + wm + 16 * i + lr + 8 * h2;
                float2 o = make_float2(acc[i][j][2 * h2 + 0] * sc0,
                                       acc[i][j][2 * h2 + 1] * sc1);
                *reinterpret_cast<float2*>(out + (size_t)m * 4096 + col) = o;
            }
        }
    }
}

// ---------------- fused causal flash attention (fp16, R10) ---- grid (64, 8)
#define FKH 136
#define FVH 136
#define FPH 72
#define SKH (64 * FKH)
#define SVH (64 * FVH)
#define FLASH_SMEM ((2 * SKH + 2 * SVH + 128 * FPH) * 2)

__device__ __forceinline__ void flash_loadT(__half* dst, const __half* src, int n0, int t) {
    int c = t & 15, rb = t >> 4;
#pragma unroll
    for (int p = 0; p < 4; ++p) {
        int r = rb + 16 * p;
        cpa16(dst + r * FKH + 8 * c, src + (size_t)(n0 + r) * 128 + 8 * c);
    }
}

__global__ __launch_bounds__(256, 1) void flash_h()
{
    extern __shared__ __half smh[];
    __half* sK = smh;
    __half* sV = smh + 2 * SKH;
    __half* sP = sV + 2 * SVH;
    const uint32_t sKa0 = static_cast<uint32_t>(__cvta_generic_to_shared(sK));
    const uint32_t sVa0 = static_cast<uint32_t>(__cvta_generic_to_shared(sV));
    const uint32_t sPa  = static_cast<uint32_t>(__cvta_generic_to_shared(sP));

    const int t = threadIdx.x, lane = t & 31, w = t >> 5;
    const int lr = lane >> 2, lc = lane & 3;
    const int arow = ((lane >> 3) & 1) * 8 + (lane & 7);
    const int acol = ((lane >> 4) & 1) * 8;
    const int brow = ((lane >> 4) & 1) * 8 + (lane & 7);
    const int bcol = ((lane >> 3) & 1) * 8;
    const int z = blockIdx.x, mt = 7 - blockIdx.y;
    const int m0 = mt * 128;
    const int niter = 2 * mt + 2;
    const int b = z >> 5, h = z & 31, kvh = h >> 2;

    const __half* Qp = g_Q + (size_t)(b * 32 + h) * 131072;
    const __half* Kp = g_K + (size_t)(b * 8 + kvh) * 131072;
    const __half* Vp = g_V + (size_t)(b * 8 + kvh) * 131072;

    {
        int c = t & 15, rb = t >> 4;
#pragma unroll
        for (int p = 0; p < 8; ++p) {
            int r = rb + 16 * p;
            __half* dst = (r < 64) ? (sK + r * FKH + 8 * c)
                                   : (sV + (r - 64) * FKH + 8 * c);
            cpa16(dst, Qp + (size_t)(m0 + r) * 128 + 8 * c);
        }
        CP_COMMIT(); CP_WAIT0();
    }
    __syncthreads();

    uint32_t qf[8][4];
    {
        const __half* base = (w < 4) ? sK : sV;
        int rb2 = (w < 4) ? 16 * w : 16 * w - 64;
#pragma unroll
        for (int s = 0; s < 8; ++s) {
            const __half* p = base + (rb2 + lr) * FKH + 16 * s + 2 * lc;
            qf[s][0] = ldu32(p);
            qf[s][1] = ldu32(p + 8 * FKH);
            qf[s][2] = ldu32(p + 8);
            qf[s][3] = ldu32(p + 8 * FKH + 8);
        }
    }
    __syncthreads();

    float oacc[16][4];
#pragma unroll
    for (int j = 0; j < 16; ++j)
#pragma unroll
        for (int q = 0; q < 4; ++q) oacc[j][q] = 0.f;
    float mrow[2] = {-1e38f, -1e38f};
    float lrow[2] = {0.f, 0.f};

    flash_loadT(sK, Kp, 0, t);
    flash_loadT(sV, Vp, 0, t);
    CP_COMMIT();

    const float sscale = 0.08838834764831845f;

    for (int it = 0; it < niter; ++it) {
        if (it + 1 < niter) {
            int nb = (it + 1) & 1;
            flash_loadT(sK + nb * SKH, Kp, (it + 1) * 64, t);
            flash_loadT(sV + nb * SVH, Vp, (it + 1) * 64, t);
            CP_COMMIT(); CP_WAIT1();
        } else CP_WAIT0();
        __syncthreads();

        const int buf = it & 1;
        const uint32_t K0a = sKa0 + buf * SKH * 2;
        const uint32_t V0a = sVa0 + buf * SVH * 2;
        const int n0 = it * 64;

        float sacc[8][4];
#pragma unroll
        for (int j = 0; j < 8; ++j)
#pragma unroll
            for (int q = 0; q < 4; ++q) sacc[j][q] = 0.f;
#pragma unroll
        for (int s = 0; s < 8; ++s) {
            uint32_t kf[4][4];
#pragma unroll
            for (int jj = 0; jj < 4; ++jj)
                ldm4(kf[jj], K0a + ((16 * jj + brow) * FKH + 16 * s + bcol) * 2);
#pragma unroll
            for (int jj = 0; jj < 4; ++jj) {
                mma_f16(sacc[2 * jj],     qf[s], kf[jj][0], kf[jj][1]);
                mma_f16(sacc[2 * jj + 1], qf[s], kf[jj][2], kf[jj][3]);
            }
        }

#pragma unroll
        for (int d = 0; d < 2; ++d) {
            const int grow = m0 + 16 * w + lr + 8 * d;
            float rm = -1e38f;
#pragma unroll
            for (int j = 0; j < 8; ++j) {
                int c0 = n0 + 8 * j + 2 * lc;
                float v0 = sacc[j][2 * d]     * sscale;
                float v1 = sacc[j][2 * d + 1] * sscale;
                if (c0     > grow) v0 = -1e30f;
                if (c0 + 1 > grow) v1 = -1e30f;
                sacc[j][2 * d]     = v0;
                sacc[j][2 * d + 1] = v1;
                rm = fmaxf(rm, fmaxf(v0, v1));
            }
            rm = fmaxf(rm, __shfl_xor_sync(0xffffffffu, rm, 1));
            rm = fmaxf(rm, __shfl_xor_sync(0xffffffffu, rm, 2));
            float newm = fmaxf(mrow[d], rm);
            float f = __expf(mrow[d] - newm);
            float rs = 0.f;
#pragma unroll
            for (int j = 0; j < 8; ++j) {
                float p0 = __expf(sacc[j][2 * d]     - newm);
                float p1 = __expf(sacc[j][2 * d + 1] - newm);
                rs += p0 + p1;
                __half2* pp = reinterpret_cast<__half2*>(
                    sP + (16 * w + lr + 8 * d) * FPH + 8 * j + 2 * lc);
                *pp = __floats2half2_rn(p0, p1);
            }
            rs += __shfl_xor_sync(0xffffffffu, rs, 1);
            rs += __shfl_xor_sync(0xffffffffu, rs, 2);
            lrow[d] = lrow[d] * f + rs;
            mrow[d] = newm;
#pragma unroll
            for (int j2 = 0; j2 < 16; ++j2) {
                oacc[j2][2 * d]     *= f;
                oacc[j2][2 * d + 1] *= f;
            }
        }
        __syncwarp();

#pragma unroll
        for (int s = 0; s < 4; ++s) {
            uint32_t af[4];
            ldm4(af, sPa + ((16 * w + arow) * FPH + 16 * s + acol) * 2);
#pragma unroll
            for (int jj = 0; jj < 8; ++jj) {
                uint32_t vf[4];
                ldm4t(vf, V0a + ((16 * s + arow) * FVH + 16 * jj + acol) * 2);
                mma_f16(oacc[2 * jj],     af, vf[0], vf[1]);
                mma_f16(oacc[2 * jj + 1], af, vf[2], vf[3]);
            }
        }
        __syncthreads();
    }

#pragma unroll
    for (int d = 0; d < 2; ++d) {
        float inv = 1.f / lrow[d];
        int grow = m0 + 16 * w + lr + 8 * d;
        __half* orow = g_AO + ((size_t)(b * 1024 + grow)) * 4096 + h * 128;
#pragma unroll
        for (int j2 = 0; j2 < 16; ++j2) {
            __half2* dst = reinterpret_cast<__half2*>(orow + 8 * j2 + 2 * lc);
            *dst = __floats2half2_rn(oacc[j2][2 * d] * inv, oacc[j2][2 * d + 1] * inv);
        }
    }
}

// =============================================================================
extern "C" void kernel_launch(void* const* d_in, const int* in_sizes, int n_in,
                              void* d_out, int out_size)
{
    const float* X    = (const float*)d_in[0];
    const float* sq   = (const float*)d_in[3];
    const float* bq   = (const float*)d_in[4];
    const float* sk   = (const float*)d_in[6];
    const float* bk   = (const float*)d_in[7];
    const float* sv   = (const float*)d_in[9];
    const float* so   = (const float*)d_in[11];
    const int*   wq   = (const int*)d_in[2];
    const int*   wk   = (const int*)d_in[5];
    const int*   wv   = (const int*)d_in[8];
    const int*   wo   = (const int*)d_in[10];
    float* out = (float*)d_out;

    cudaFuncSetAttribute(qkv_h,   cudaFuncAttributeMaxDynamicSharedMemorySize, SMEM_G);
    cudaFuncSetAttribute(o_h,     cudaFuncAttributeMaxDynamicSharedMemorySize, SMEM_G);
    cudaFuncSetAttribute(flash_h, cudaFuncAttributeMaxDynamicSharedMemorySize, FLASH_SMEM);

    __half* Xh = nullptr; cudaGetSymbolAddress((void**)&Xh, g_Xh);
    __half* W  = nullptr; cudaGetSymbolAddress((void**)&W,  g_W);
    __half* Wo = nullptr; cudaGetSymbolAddress((void**)&Wo, g_Wo);

    x2h_kernel<<<2048 * 4096 / 32 / 256, 256>>>(X, Xh, 2048 * 4096 / 32);
    w2h_kernel<<<4096 * 4096 / 32 / 256, 256>>>(wq, W,               4096 * 4096 / 32);
    w2h_kernel<<<1024 * 4096 / 32 / 256, 256>>>(wk, W + 4096 * 4096, 1024 * 4096 / 32);
    w2h_kernel<<<1024 * 4096 / 32 / 256, 256>>>(wv, W + 5120 * 4096, 1024 * 4096 / 32);
    w2h_kernel<<<4096 * 4096 / 32 / 256, 256>>>(wo, Wo,              4096 * 4096 / 32);

    qkv_h<<<dim3(16, 48), 256, SMEM_G>>>(sq, bq, sk, bk, sv);
    flash_h<<<dim3(64, 8), 256, FLASH_SMEM>>>();
    o_h<<<dim3(16, 32), 256, SMEM_G>>>(so, out);
}